// round 3
// baseline (speedup 1.0000x reference)
#include <cuda_runtime.h>
#include <math.h>

#define BATCH 4096
#define INF   128
#define OUTF  128
#define POST_STRIDE (OUTF * INF)      // 16384 floats per batch row of postacts
#define Y_ELEMS (BATCH * OUTF)        // 524288

// Scratch for x_red = x @ mask^T  (4096 x 128 fp32 = 2 MB). __device__ global:
// allowed (no dynamic allocation).
__device__ float g_xred[BATCH * INF];

// ---------------------------------------------------------------------------
// Kernel 1: x_red[b, j] = sum_i x[b, i] * mask[j, i]
// Grid: 256 blocks (b-tile of 16), 256 threads.
// Register-tiled: thread handles (8 b) x (1 j), float4 over i.
// smem row stride 36 floats (144 B) -> 16B-aligned float4 rows, conflict-free.
// ---------------------------------------------------------------------------
__global__ __launch_bounds__(256) void xred_kernel(const float* __restrict__ x,
                                                   const float* __restrict__ mask) {
    __shared__ float smk[128][36];   // mask chunk: [j][ii]
    __shared__ float sxx[16][36];    // x chunk:    [b][ii]

    const int tid = threadIdx.x;
    const int b0  = blockIdx.x * 16;
    const int jl  = tid & 127;          // this thread's j
    const int bg  = (tid >> 7) * 8;     // base of this thread's 8 b rows

    float acc[8];
#pragma unroll
    for (int k = 0; k < 8; ++k) acc[k] = 0.0f;

    for (int c = 0; c < 4; ++c) {       // 4 chunks of 32 i
        __syncthreads();
        const int i0 = c * 32;
        // load mask chunk (coalesced over ii)
        for (int idx = tid; idx < 128 * 32; idx += 256) {
            int jj = idx >> 5, ii = idx & 31;
            smk[jj][ii] = mask[jj * INF + i0 + ii];
        }
        // load x chunk (coalesced over ii)
        for (int idx = tid; idx < 16 * 32; idx += 256) {
            int bb = idx >> 5, ii = idx & 31;
            sxx[bb][ii] = x[(size_t)(b0 + bb) * INF + i0 + ii];
        }
        __syncthreads();

#pragma unroll
        for (int q = 0; q < 8; ++q) {
            float4 m4 = *reinterpret_cast<const float4*>(&smk[jl][q * 4]);
#pragma unroll
            for (int bb = 0; bb < 8; ++bb) {
                float4 x4 = *reinterpret_cast<const float4*>(&sxx[bg + bb][q * 4]);
                acc[bb] += m4.x * x4.x + m4.y * x4.y + m4.z * x4.z + m4.w * x4.w;
            }
        }
    }

#pragma unroll
    for (int bb = 0; bb < 8; ++bb)
        g_xred[(size_t)(b0 + bg + bb) * INF + jl] = acc[bb];   // lanes: consecutive j -> coalesced
}

// ---------------------------------------------------------------------------
// Kernel 2: main KAN layer.
// Grid: (r = 128, b_tile = 128), 256 threads (8 warps).
// Warp w handles i in [w*16, w*16+16); lanes map to the 32 batch rows of the
// tile -> the fun_id switch is UNIFORM per warp-iteration (no divergence).
// postacts tile staged in smem (stride 129: conflict-free column writes and
// row reads), then written fully coalesced. y reduced via smem partials.
// ---------------------------------------------------------------------------
__global__ __launch_bounds__(256) void kan_kernel(const float* __restrict__ affine,
                                                  const int*   __restrict__ fids,
                                                  float*       __restrict__ out) {
    const int r  = blockIdx.x;
    const int b0 = blockIdx.y << 5;         // 32-batch tile

    __shared__ float sx[32][129];
    __shared__ float so[32][129];
    __shared__ float sa[128], sb[128], sc[128], sd[128];
    __shared__ int   sf[128];
    __shared__ float spart[8][32];

    const int tid = threadIdx.x;

    if (tid < 128) {
        float4 v = reinterpret_cast<const float4*>(affine)[r * 128 + tid]; // affine[r][i][0..3]
        sa[tid] = v.x; sb[tid] = v.y; sc[tid] = v.z; sd[tid] = v.w;
        sf[tid] = fids[r * 128 + tid];
    }
#pragma unroll
    for (int k = 0; k < 16; ++k) {
        int idx = tid + k * 256;
        int b = idx >> 7, i = idx & 127;
        sx[b][i] = g_xred[(size_t)(b0 + b) * INF + i];   // coalesced
    }
    __syncthreads();

    const int lane = tid & 31;
    const int w    = tid >> 5;

    float acc = 0.0f;
#pragma unroll 4
    for (int k = 0; k < 16; ++k) {
        const int   i  = (w << 4) + k;
        const float z  = fmaf(sa[i], sx[lane][i], sb[i]);   // stride-129: conflict-free
        const int   id = sf[i];                             // uniform across warp
        float f;
        switch (id) {
            case 0: f = z; break;
            case 1: f = z * z; break;
            case 2: f = z * z * z; break;
            case 3: f = sinf(z); break;
            case 4: f = tanhf(z); break;
            case 5: f = 1.0f / (1.0f + expf(-z)); break;
            case 6: f = expf(-z * z); break;
            case 7: f = fabsf(z); break;
            case 8: f = atanf(z); break;
            default: f = expf(z); break;                    // id == 9
        }
        const float p = fmaf(sc[i], f, sd[i]);
        so[lane][i] = p;                                    // conflict-free
        acc += p;
    }
    spart[w][lane] = acc;
    __syncthreads();

    // Coalesced write of the 32x128 postacts tile.
    float* post = out + Y_ELEMS + (size_t)b0 * POST_STRIDE + (size_t)r * INF;
#pragma unroll
    for (int k = 0; k < 16; ++k) {
        int idx = tid + k * 256;
        int b = idx >> 7, i = idx & 127;
        post[(size_t)b * POST_STRIDE + i] = so[b][i];
    }

    // y[b, r] = sum_i postacts
    if (tid < 32) {
        float s = spart[0][tid];
#pragma unroll
        for (int ww = 1; ww < 8; ++ww) s += spart[ww][tid];
        out[(size_t)(b0 + tid) * OUTF + r] = s;
    }
}

// ---------------------------------------------------------------------------
extern "C" void kernel_launch(void* const* d_in, const int* in_sizes, int n_in,
                              void* d_out, int out_size) {
    const float* x      = (const float*)d_in[0];
    const float* affine = (const float*)d_in[1];
    const float* mask   = (const float*)d_in[2];
    const int*   fid    = (const int*)d_in[3];
    float*       out    = (float*)d_out;

    (void)in_sizes; (void)n_in; (void)out_size;

    xred_kernel<<<BATCH / 16, 256>>>(x, mask);
    kan_kernel<<<dim3(OUTF, BATCH / 32), 256>>>(affine, fid, out);
}

// round 6
// speedup vs baseline: 1.3103x; 1.3103x over previous
#include <cuda_runtime.h>
#include <math.h>

#define BATCH 4096
#define INF   128
#define OUTF  128
#define POST_STRIDE (OUTF * INF)      // 16384 floats per batch row of postacts
#define Y_ELEMS (BATCH * OUTF)        // 524288

// Scratch for x_red = x @ mask^T (4096 x 128 fp32 = 2 MB). Static device global.
__device__ float g_xred[BATCH * INF];

// ---------------------------------------------------------------------------
// Kernel 1: x_red[b, j] = sum_i x[b, i] * mask[j, i]
// 512 blocks (8 b-rows each) x 128 threads (thread = one j). One sync.
// x tile in smem (broadcast reads), mask rows streamed via LDG.128 (L1-resident).
// ---------------------------------------------------------------------------
__global__ __launch_bounds__(128) void xred_kernel(const float* __restrict__ x,
                                                   const float* __restrict__ mask) {
    __shared__ float4 sx4[8][32];          // 8 b-rows x 128 floats

    const int tid = threadIdx.x;           // j
    const int b0  = blockIdx.x * 8;

    const float4* x4 = reinterpret_cast<const float4*>(x) + (size_t)b0 * 32;
#pragma unroll
    for (int k = 0; k < 2; ++k) {
        int idx = tid + k * 128;           // 0..255
        sx4[idx >> 5][idx & 31] = x4[idx];
    }
    __syncthreads();

    const float4* m4 = reinterpret_cast<const float4*>(mask) + (size_t)tid * 32;

    float acc[8];
#pragma unroll
    for (int b = 0; b < 8; ++b) acc[b] = 0.0f;

#pragma unroll 8
    for (int q = 0; q < 32; ++q) {
        float4 mv = __ldg(&m4[q]);
#pragma unroll
        for (int b = 0; b < 8; ++b) {
            float4 xv = sx4[b][q];         // broadcast: conflict-free
            acc[b] += mv.x * xv.x + mv.y * xv.y + mv.z * xv.z + mv.w * xv.w;
        }
    }

#pragma unroll
    for (int b = 0; b < 8; ++b)
        g_xred[(size_t)(b0 + b) * INF + tid] = acc[b];   // lanes: consecutive j -> coalesced
}

// ---------------------------------------------------------------------------
// Activation body. `id` is warp-uniform at every call site -> single branch
// taken per warp. MUFU-based fast paths (abs err ~1e-6), atanf stays libm.
// ---------------------------------------------------------------------------
__device__ __forceinline__ float apply_fn(int id, float z) {
    switch (id) {
        case 0: return z;
        case 1: return z * z;
        case 2: return z * z * z;
        case 3: return __sinf(z);
        case 4: {                                   // tanh, saturates correctly at +/-inf
            float e = __expf(2.0f * z);
            return 1.0f - 2.0f * __fdividef(1.0f, e + 1.0f);
        }
        case 5: return __fdividef(1.0f, 1.0f + __expf(-z));   // sigmoid
        case 6: return __expf(-z * z);
        case 7: return fabsf(z);
        case 8: return atanf(z);
        default: return __expf(z);                  // id == 9
    }
}

// ---------------------------------------------------------------------------
// Kernel 2: main KAN layer.
// Grid: (r = 128, b_tile = 128), 256 threads (8 warps).
// Warp w owns i in [w*16, w*16+16); lanes map to the 32 batch rows of the
// tile -> fun_id is UNIFORM per warp-iteration (no divergence).
// All smem traffic is 128-bit: affine as float4, z-in/out processed 4-wide
// on stride-132 rows (bank = 4*lane + i0 mod 32: conflict-free per phase).
// postacts tile staged in smem then streamed out with STG.128, fully coalesced.
// ---------------------------------------------------------------------------
__global__ __launch_bounds__(256) void kan_kernel(const float4* __restrict__ affine4,
                                                  const int*   __restrict__ fids,
                                                  float*       __restrict__ out) {
    const int r  = blockIdx.x;
    const int b0 = blockIdx.y << 5;        // 32-batch tile

    __shared__ float  sx[32][132];
    __shared__ float  so[32][132];
    __shared__ float4 saf[128];            // affine[r][i][0..3]
    __shared__ int    sf[128];
    __shared__ float  spart[8][32];

    const int tid = threadIdx.x;

    if (tid < 128) {
        saf[tid] = affine4[r * 128 + tid];
        sf[tid]  = fids[r * 128 + tid];
    }
    {   // prologue: 32x128 x_red tile, LDG.128 + STS.128
        const float4* xr4 = reinterpret_cast<const float4*>(g_xred) + (size_t)b0 * 32;
#pragma unroll
        for (int k = 0; k < 4; ++k) {
            int idx = tid + k * 256;       // 0..1023
            int b = idx >> 5, i4 = idx & 31;
            *reinterpret_cast<float4*>(&sx[b][i4 * 4]) = xr4[b * 32 + i4];
        }
    }
    __syncthreads();

    const int lane = tid & 31;
    const int w    = tid >> 5;
    const int iw   = w << 4;

    float acc = 0.0f;
#pragma unroll
    for (int g = 0; g < 4; ++g) {
        const int i0 = iw + g * 4;
        float4 xv = *reinterpret_cast<const float4*>(&sx[lane][i0]);   // LDS.128
        float4 pv;
        {
            float4 af = saf[i0 + 0];                                   // LDS.128
            float  z  = fmaf(af.x, xv.x, af.y);
            pv.x = fmaf(af.z, apply_fn(sf[i0 + 0], z), af.w);
        }
        {
            float4 af = saf[i0 + 1];
            float  z  = fmaf(af.x, xv.y, af.y);
            pv.y = fmaf(af.z, apply_fn(sf[i0 + 1], z), af.w);
        }
        {
            float4 af = saf[i0 + 2];
            float  z  = fmaf(af.x, xv.z, af.y);
            pv.z = fmaf(af.z, apply_fn(sf[i0 + 2], z), af.w);
        }
        {
            float4 af = saf[i0 + 3];
            float  z  = fmaf(af.x, xv.w, af.y);
            pv.w = fmaf(af.z, apply_fn(sf[i0 + 3], z), af.w);
        }
        *reinterpret_cast<float4*>(&so[lane][i0]) = pv;                // STS.128
        acc += (pv.x + pv.y) + (pv.z + pv.w);
    }
    spart[w][lane] = acc;
    __syncthreads();

    // epilogue: stream 32x128 tile to postacts, LDS.128 + STG.128, coalesced
    float* post = out + Y_ELEMS + (size_t)b0 * POST_STRIDE + (size_t)r * INF;
#pragma unroll
    for (int k = 0; k < 4; ++k) {
        int idx = tid + k * 256;
        int b = idx >> 5, i4 = idx & 31;
        float4 v = *reinterpret_cast<const float4*>(&so[b][i4 * 4]);
        *reinterpret_cast<float4*>(&post[(size_t)b * POST_STRIDE + i4 * 4]) = v;
    }

    // y[b, r] = sum_i postacts[b, r, i]
    if (tid < 32) {
        float s = spart[0][tid];
#pragma unroll
        for (int ww = 1; ww < 8; ++ww) s += spart[ww][tid];
        out[(size_t)(b0 + tid) * OUTF + r] = s;
    }
}

// ---------------------------------------------------------------------------
extern "C" void kernel_launch(void* const* d_in, const int* in_sizes, int n_in,
                              void* d_out, int out_size) {
    const float*  x      = (const float*)d_in[0];
    const float4* affine = (const float4*)d_in[1];
    const float*  mask   = (const float*)d_in[2];
    const int*    fid    = (const int*)d_in[3];
    float*        out    = (float*)d_out;

    (void)in_sizes; (void)n_in; (void)out_size;

    xred_kernel<<<BATCH / 8, 128>>>(x, mask);
    kan_kernel<<<dim3(OUTF, BATCH / 32), 256>>>(affine, fid, out);
}

// round 7
// speedup vs baseline: 1.4453x; 1.1030x over previous
#include <cuda_runtime.h>
#include <math.h>

#define BATCH 4096
#define INF   128
#define OUTF  128
#define POST_STRIDE (OUTF * INF)      // 16384 floats per batch row of postacts
#define Y_ELEMS (BATCH * OUTF)        // 524288

// x_red stored TILE-TRANSPOSED for kan's access pattern:
// g_xredT4[i4][b] = float4( x_red[b][4*i4 .. 4*i4+3] ),  i4 in [0,32), b in [0,4096).
// 2 MB static device scratch (no dynamic allocation).
__device__ float4 g_xredT4[INF / 4][BATCH];

// ---------------------------------------------------------------------------
// Kernel 1: x_red[b, j] = sum_i x[b, i] * mask[j, i], written transposed.
// 1024 blocks (4 b-rows each) x 128 threads (thread = one j). One sync.
// ---------------------------------------------------------------------------
__global__ __launch_bounds__(128) void xred_kernel(const float* __restrict__ x,
                                                   const float* __restrict__ mask) {
    __shared__ float4 sx4[4][32];          // 4 b-rows x 128 floats

    const int tid = threadIdx.x;           // j
    const int b0  = blockIdx.x * 4;

    const float4* x4 = reinterpret_cast<const float4*>(x) + (size_t)b0 * 32;
    sx4[tid >> 5][tid & 31] = x4[tid];
    __syncthreads();

    const float4* m4 = reinterpret_cast<const float4*>(mask) + (size_t)tid * 32;

    float acc[4] = {0.0f, 0.0f, 0.0f, 0.0f};
#pragma unroll 8
    for (int q = 0; q < 32; ++q) {
        float4 mv = __ldg(&m4[q]);
#pragma unroll
        for (int b = 0; b < 4; ++b) {
            float4 xv = sx4[b][q];         // broadcast: conflict-free
            acc[b] += mv.x * xv.x + mv.y * xv.y + mv.z * xv.z + mv.w * xv.w;
        }
    }

    const int i4   = tid >> 2;             // which float4 group of i
    const int comp = tid & 3;              // component within the float4
#pragma unroll
    for (int b = 0; b < 4; ++b)
        reinterpret_cast<float*>(&g_xredT4[i4][b0 + b])[comp] = acc[b];
}

// ---------------------------------------------------------------------------
// Activation body. `id` is warp-uniform at every call site -> single branch
// taken per warp. MUFU-based fast paths (abs err ~1e-6), atanf stays libm.
// ---------------------------------------------------------------------------
__device__ __forceinline__ float apply_fn(int id, float z) {
    switch (id) {
        case 0: return z;
        case 1: return z * z;
        case 2: return z * z * z;
        case 3: return __sinf(z);
        case 4: {                                   // tanh, saturates correctly at +/-inf
            float e = __expf(2.0f * z);
            return 1.0f - 2.0f * __fdividef(1.0f, e + 1.0f);
        }
        case 5: return __fdividef(1.0f, 1.0f + __expf(-z));   // sigmoid
        case 6: return __expf(-z * z);
        case 7: return fabsf(z);
        case 8: return atanf(z);
        default: return __expf(z);                  // id == 9
    }
}

// ---------------------------------------------------------------------------
// Kernel 2: main KAN layer.
// Grid: (r = 128, b_tile = 128), 256 threads (8 warps).
// Warp w owns i in [w*16, w*16+16); lanes map to the 32 batch rows of the
// tile -> fun_id is UNIFORM per warp-iteration (no divergence).
// x_red arrives via ONE coalesced LDG.128 per thread per 4-i group from the
// pre-transposed g_xredT4 (no smem staging of x at all). postacts tile staged
// in so[] (stride 132: conflict-free both phases), streamed out with STG.128
// (__stcs: streaming, keep x_redT resident in L2). y via smem partials.
// ---------------------------------------------------------------------------
__global__ __launch_bounds__(256) void kan_kernel(const float4* __restrict__ affine4,
                                                  const int*   __restrict__ fids,
                                                  float*       __restrict__ out) {
    const int r  = blockIdx.x;
    const int b0 = blockIdx.y << 5;        // 32-batch tile

    __shared__ float  so[32][132];
    __shared__ float4 saf[128];            // affine[r][i][0..3]
    __shared__ int4   sf4[32];             // fun_ids packed 4-wide
    __shared__ float  spart[8][32];

    const int tid = threadIdx.x;

    if (tid < 128) {
        saf[tid] = affine4[r * 128 + tid];
    } else if (tid < 160) {
        sf4[tid - 128] = reinterpret_cast<const int4*>(fids)[r * 32 + (tid - 128)];
    }
    __syncthreads();

    const int lane = tid & 31;
    const int w    = tid >> 5;
    const int i4w  = w << 2;               // first i4 group of this warp

    // Front-batched, fully coalesced x loads (lanes = consecutive b).
    float4 xv[4];
#pragma unroll
    for (int g = 0; g < 4; ++g)
        xv[g] = g_xredT4[i4w + g][b0 + lane];

    float acc = 0.0f;
#pragma unroll
    for (int g = 0; g < 4; ++g) {
        const int  i4  = i4w + g;
        const int  i0  = i4 << 2;
        const int4 id4 = sf4[i4];          // 1 LDS.128 broadcast
        float4 pv;
        {
            float4 af = saf[i0 + 0];       // LDS.128 broadcast
            pv.x = fmaf(af.z, apply_fn(id4.x, fmaf(af.x, xv[g].x, af.y)), af.w);
        }
        {
            float4 af = saf[i0 + 1];
            pv.y = fmaf(af.z, apply_fn(id4.y, fmaf(af.x, xv[g].y, af.y)), af.w);
        }
        {
            float4 af = saf[i0 + 2];
            pv.z = fmaf(af.z, apply_fn(id4.z, fmaf(af.x, xv[g].z, af.y)), af.w);
        }
        {
            float4 af = saf[i0 + 3];
            pv.w = fmaf(af.z, apply_fn(id4.w, fmaf(af.x, xv[g].w, af.y)), af.w);
        }
        *reinterpret_cast<float4*>(&so[lane][i0]) = pv;    // STS.128, conflict-free
        acc += (pv.x + pv.y) + (pv.z + pv.w);
    }
    spart[w][lane] = acc;
    __syncthreads();

    // Epilogue: stream 32x128 tile to postacts, LDS.128 + STG.128, coalesced.
    float* post = out + Y_ELEMS + (size_t)b0 * POST_STRIDE + (size_t)r * INF;
#pragma unroll
    for (int k = 0; k < 4; ++k) {
        int idx = tid + k * 256;
        int b = idx >> 5, i4 = idx & 31;
        float4 v = *reinterpret_cast<const float4*>(&so[b][i4 * 4]);
        __stcs(reinterpret_cast<float4*>(&post[(size_t)b * POST_STRIDE + i4 * 4]), v);
    }

    // y[b, r] = sum_i postacts[b, r, i]
    if (tid < 32) {
        float s = spart[0][tid];
#pragma unroll
        for (int ww = 1; ww < 8; ++ww) s += spart[ww][tid];
        out[(size_t)(b0 + tid) * OUTF + r] = s;
    }
}

// ---------------------------------------------------------------------------
extern "C" void kernel_launch(void* const* d_in, const int* in_sizes, int n_in,
                              void* d_out, int out_size) {
    const float*  x      = (const float*)d_in[0];
    const float4* affine = (const float4*)d_in[1];
    const float*  mask   = (const float*)d_in[2];
    const int*    fid    = (const int*)d_in[3];
    float*        out    = (float*)d_out;

    (void)in_sizes; (void)n_in; (void)out_size;

    xred_kernel<<<BATCH / 4, 128>>>(x, mask);
    kan_kernel<<<dim3(OUTF, BATCH / 32), 256>>>(affine, fid, out);
}